// round 7
// baseline (speedup 1.0000x reference)
#include <cuda_runtime.h>

#define BATCH  128
#define TSTEPS 512
#define FEAT   64
#define UN1    256
#define UN2    128

// packed fp32x2 FMA (Blackwell): two fp32 FMAs per instruction
#define FMA2(acc, a, b) \
  asm("fma.rn.f32x2 %0, %1, %2, %0;" : "+l"(acc) : "l"(a), "l"(b))
#define SPLAT2(dst, x) \
  asm("mov.b64 %0, {%1, %1};" : "=l"(dst) : "r"(__float_as_uint(x)))

#define CP_ASYNC16(saddr, gaddr) \
  asm volatile("cp.async.cg.shared.global [%0], [%1], 16;" :: "r"(saddr), "l"(gaddr))
#define CP_COMMIT() asm volatile("cp.async.commit_group;")
#define CP_WAIT0()  asm volatile("cp.async.wait_group 0;")

// ---------------- scratch ------------------------------------------------------
__device__ float g_hseq1[(size_t)(TSTEPS + 1) * UN1 * BATCH];  // [t][u][b], slot0 = 0
__device__ float g_hseq2[(size_t)(TSTEPS + 1) * UN2 * BATCH];  // [t][u][b], slot0 = 0
__device__ unsigned g_barA[4], g_barB[4], g_exit[4];           // per batch-group

// ---------------- fused persistent 2-layer LSTM --------------------------------
// 128 CTAs = 4 bg (32 batches) x 32 ug.
// Split barriers: A seals h1 stores (arrive mid-iter, right after h1 store);
// B seals h2 stores (arrive at iter end; wait deferred to mid-iter).
__global__ void __launch_bounds__(256)
lstm_fused(const float* __restrict__ x,
           const float* __restrict__ W1, const float* __restrict__ U1m,
           const float* __restrict__ b1,
           const float* __restrict__ W2, const float* __restrict__ U2m,
           const float* __restrict__ b2,
           float* __restrict__ out_last) {
  constexpr int SHS  = 36;   // sH / sH2e row stride
  constexpr int SXS  = 33;   // sX row stride (2-way writes, CF scalar reads)
  constexpr int ZPS  = 33;   // sZp1: [q][col32][bl] stride 33 (2-way st, CF ld)
  constexpr int ZP2S = 34;   // sZp2: [q][col16][bl] stride 34 (2-way st, CF ld)

  extern __shared__ float smem[];
  float* sU1  = smem;                   // [256][32]
  float* sW1x = sU1 + 256 * 32;         // [64][32]
  float* sUW2 = sW1x + 64 * 32;         // [384][16]  W2 | U2
  float* sH   = sUW2 + 384 * 16;        // [256][SHS] h1_{t-1} [k][b]
  float* sH2e = sH + 256 * SHS;         // [128][SHS] h2_{t-2} [k][b]
  float* sX   = sH2e + 128 * SHS;       // [64][SXS]  x_t [f][b]
  float* sZp1 = sX + 64 * SXS;          // [8][32][ZPS]
  float* sZp2 = sZp1 + 8 * 32 * ZPS;    // [8][16][ZP2S]

  const int tid = threadIdx.x;
  const int bg  = blockIdx.x >> 5;
  const int ug  = blockIdx.x & 31;
  const int b0  = bg * 32;
  unsigned* barA  = &g_barA[bg];
  unsigned* barB  = &g_barB[bg];
  unsigned* exitc = &g_exit[bg];

  // ---- weight slices (once) ----
  for (int i = tid; i < 256 * 32; i += 256) {
    int k = i >> 5, cc = i & 31;
    sU1[i] = U1m[(size_t)k * 1024 + (cc >> 3) * 256 + ug * 8 + (cc & 7)];
  }
  for (int i = tid; i < 64 * 32; i += 256) {
    int k = i >> 5, cc = i & 31;
    sW1x[i] = W1[(size_t)k * 1024 + (cc >> 3) * 256 + ug * 8 + (cc & 7)];
  }
  for (int i = tid; i < 384 * 16; i += 256) {
    int k = i >> 4, c = i & 15;
    int col = (c >> 2) * 128 + ug * 4 + (c & 3);
    sUW2[i] = (k < 256) ? W2[(size_t)k * 512 + col]
                        : U2m[(size_t)(k - 256) * 512 + col];
  }

  // ---- thread mappings ----
  const int q  = tid >> 5;           // warp = k-slice
  const int li = tid & 31;
  const int tm = li >> 2;            // rows 4*tm..+3
  const int tn = li & 3;             // gate

  const int uu  = tid >> 5;          // L1 epilogue unit
  const int bl  = tid & 31;
  const int b_g = b0 + bl;
  const int u_g = ug * 8 + uu;
  const int uu2  = (tid >> 5) & 3;   // L2 epilogue unit (tid<128)
  const int u_g2 = ug * 4 + uu2;

  float c1 = 0.f, c2 = 0.f;
  float b1g[4], b2g[4];
#pragma unroll
  for (int g = 0; g < 4; g++) b1g[g] = b1[g * 256 + u_g];
  if (tid < 128) {
#pragma unroll
    for (int g = 0; g < 4; g++) b2g[g] = b2[g * 128 + u_g2];
  }

  const unsigned sH_u   = (unsigned)__cvta_generic_to_shared(sH);
  const unsigned sH2e_u = (unsigned)__cvta_generic_to_shared(sH2e);

  // ---- init h_{-1}, first arrives, stage sX(t=0) ----
  g_hseq1[(size_t)u_g * BATCH + b_g] = 0.f;
  if (tid < 128) g_hseq2[(size_t)u_g2 * BATCH + b_g] = 0.f;
  __syncthreads();
  if (tid == 0) {
    asm volatile("red.release.gpu.global.add.u32 [%0], %1;" :: "l"(barA), "r"(1u));
    asm volatile("red.release.gpu.global.add.u32 [%0], %1;" :: "l"(barB), "r"(1u));
  }
  for (int i = tid; i < 512; i += 256) {
    int bb = i >> 4, f4 = (i & 15) << 2;
    float4 v = *(const float4*)(x + (size_t)(b0 + bb) * TSTEPS * FEAT + f4);
    sX[(f4 + 0) * SXS + bb] = v.x;
    sX[(f4 + 1) * SXS + bb] = v.y;
    sX[(f4 + 2) * SXS + bb] = v.z;
    sX[(f4 + 3) * SXS + bb] = v.w;
  }

  for (int t = 0; t <= TSTEPS; t++) {
    const unsigned tgt = (unsigned)(t + 1) * 32u;

    // ---- wait A: h1_{t-1} sealed (steady-state: already satisfied) ----
    if (tid == 0) {
      unsigned v;
      do {
        asm volatile("ld.relaxed.gpu.global.u32 %0, [%1];" : "=r"(v) : "l"(barA));
      } while (v < tgt);
      asm volatile("ld.acquire.gpu.global.u32 %0, [%1];" : "=r"(v) : "l"(barA));
    }
    __syncthreads();                                   // S1

    // ---- stage sH = h1_{t-1} ----
    {
      const float* hp = g_hseq1 + (size_t)t * UN1 * BATCH + b0;
#pragma unroll
      for (int j = 0; j < 8; j++) {
        int i = tid + j * 256;
        int k = i >> 3, b4 = (i & 7) << 2;
        CP_ASYNC16(sH_u + (unsigned)(k * SHS + b4) * 4u,
                   hp + (size_t)k * BATCH + b4);
      }
    }
    CP_COMMIT();

    // ---- L1 x-part while copies fly ----
    unsigned long long acc[4][4];
#pragma unroll
    for (int r = 0; r < 4; r++)
#pragma unroll
      for (int c = 0; c < 4; c++) acc[r][c] = 0ull;
    if (t < TSTEPS) {
#pragma unroll
      for (int kk = 0; kk < 8; kk++) {
        int k = q * 8 + kk;
        const float* ap = sX + k * SXS + 4 * tm;
        float a0 = ap[0], a1 = ap[1], a2 = ap[2], a3 = ap[3];
        ulonglong2 uA = *(const ulonglong2*)(sW1x + k * 32 + 8 * tn);
        ulonglong2 uB = *(const ulonglong2*)(sW1x + k * 32 + 8 * tn + 4);
        unsigned long long s0, s1, s2, s3;
        SPLAT2(s0, a0); SPLAT2(s1, a1); SPLAT2(s2, a2); SPLAT2(s3, a3);
        FMA2(acc[0][0], s0, uA.x); FMA2(acc[0][1], s0, uA.y);
        FMA2(acc[0][2], s0, uB.x); FMA2(acc[0][3], s0, uB.y);
        FMA2(acc[1][0], s1, uA.x); FMA2(acc[1][1], s1, uA.y);
        FMA2(acc[1][2], s1, uB.x); FMA2(acc[1][3], s1, uB.y);
        FMA2(acc[2][0], s2, uA.x); FMA2(acc[2][1], s2, uA.y);
        FMA2(acc[2][2], s2, uB.x); FMA2(acc[2][3], s2, uB.y);
        FMA2(acc[3][0], s3, uA.x); FMA2(acc[3][1], s3, uA.y);
        FMA2(acc[3][2], s3, uB.x); FMA2(acc[3][3], s3, uB.y);
      }
    }
    CP_WAIT0();
    __syncthreads();                                   // S2

    // ---- L1 h-part + partial stores ----
    if (t < TSTEPS) {
#pragma unroll 8
      for (int kk = 0; kk < 32; kk++) {
        int k = q * 32 + kk;
        float4 a = *(const float4*)(sH + k * SHS + 4 * tm);
        ulonglong2 uA = *(const ulonglong2*)(sU1 + k * 32 + 8 * tn);
        ulonglong2 uB = *(const ulonglong2*)(sU1 + k * 32 + 8 * tn + 4);
        unsigned long long s0, s1, s2, s3;
        SPLAT2(s0, a.x); SPLAT2(s1, a.y); SPLAT2(s2, a.z); SPLAT2(s3, a.w);
        FMA2(acc[0][0], s0, uA.x); FMA2(acc[0][1], s0, uA.y);
        FMA2(acc[0][2], s0, uB.x); FMA2(acc[0][3], s0, uB.y);
        FMA2(acc[1][0], s1, uA.x); FMA2(acc[1][1], s1, uA.y);
        FMA2(acc[1][2], s1, uB.x); FMA2(acc[1][3], s1, uB.y);
        FMA2(acc[2][0], s2, uA.x); FMA2(acc[2][1], s2, uA.y);
        FMA2(acc[2][2], s2, uB.x); FMA2(acc[2][3], s2, uB.y);
        FMA2(acc[3][0], s3, uA.x); FMA2(acc[3][1], s3, uA.y);
        FMA2(acc[3][2], s3, uB.x); FMA2(acc[3][3], s3, uB.y);
      }
      // scalar stores into [q][col][bl] (2-way conflicts max)
#pragma unroll
      for (int r = 0; r < 4; r++) {
#pragma unroll
        for (int p = 0; p < 4; p++) {
          float lo = __uint_as_float((unsigned)(acc[r][p] & 0xffffffffu));
          float hi = __uint_as_float((unsigned)(acc[r][p] >> 32));
          sZp1[(q * 32 + 8 * tn + 2 * p)     * ZPS + 4 * tm + r] = lo;
          sZp1[(q * 32 + 8 * tn + 2 * p + 1) * ZPS + 4 * tm + r] = hi;
        }
      }
    }
    __syncthreads();                                   // S3

    // ---- L1 epilogue: conflict-free reduce + h1 store ----
    if (t < TSTEPS) {
      float z[4];
#pragma unroll
      for (int g = 0; g < 4; g++) {
        float s = b1g[g];
#pragma unroll
        for (int q2 = 0; q2 < 8; q2++)
          s += sZp1[(q2 * 32 + g * 8 + uu) * ZPS + bl];
        z[g] = s;
      }
      float ig = 1.f / (1.f + __expf(-z[0]));
      float fg = 1.f / (1.f + __expf(-z[1]));
      float gg = fmaxf(z[2], 0.f);
      float og = 1.f / (1.f + __expf(-z[3]));
      c1 = fg * c1 + ig * gg;
      float h = og * fmaxf(c1, 0.f);
      g_hseq1[(size_t)(t + 1) * UN1 * BATCH + (size_t)u_g * BATCH + b_g] = h;
    }
    __syncthreads();                                   // S4 (h1 sealed)
    if (tid == 0 && t < TSTEPS)
      asm volatile("red.release.gpu.global.add.u32 [%0], %1;" :: "l"(barA), "r"(1u));

    // ================= L2 phase (off the h1 critical path) =================
    if (t >= 1) {
      // wait B: h2_{t-2} sealed (steady-state: already satisfied)
      if (tid == 0) {
        unsigned v;
        do {
          asm volatile("ld.relaxed.gpu.global.u32 %0, [%1];" : "=r"(v) : "l"(barB));
        } while (v < tgt);
        asm volatile("ld.acquire.gpu.global.u32 %0, [%1];" : "=r"(v) : "l"(barB));
      }
      __syncthreads();                                 // S5

      // stage sH2e = h2_{t-2} (flies during W2-loop)
      {
        const float* hp = g_hseq2 + (size_t)(t - 1) * UN2 * BATCH + b0;
#pragma unroll
        for (int j = 0; j < 4; j++) {
          int i = tid + j * 256;
          int k = i >> 3, b4 = (i & 7) << 2;
          CP_ASYNC16(sH2e_u + (unsigned)(k * SHS + b4) * 4u,
                     hp + (size_t)k * BATCH + b4);
        }
      }
      CP_COMMIT();

      // W2-part over h1_{t-1} (sH still resident)
      unsigned long long acc2[4][2];
#pragma unroll
      for (int r = 0; r < 4; r++) { acc2[r][0] = 0ull; acc2[r][1] = 0ull; }
#pragma unroll 8
      for (int kk = 0; kk < 32; kk++) {
        int k = q * 32 + kk;
        float4 a = *(const float4*)(sH + k * SHS + 4 * tm);
        ulonglong2 u2 = *(const ulonglong2*)(sUW2 + k * 16 + 4 * tn);
        unsigned long long s0, s1, s2, s3;
        SPLAT2(s0, a.x); SPLAT2(s1, a.y); SPLAT2(s2, a.z); SPLAT2(s3, a.w);
        FMA2(acc2[0][0], s0, u2.x); FMA2(acc2[0][1], s0, u2.y);
        FMA2(acc2[1][0], s1, u2.x); FMA2(acc2[1][1], s1, u2.y);
        FMA2(acc2[2][0], s2, u2.x); FMA2(acc2[2][1], s2, u2.y);
        FMA2(acc2[3][0], s3, u2.x); FMA2(acc2[3][1], s3, u2.y);
      }
      CP_WAIT0();
      __syncthreads();                                 // S6

      // U2-part over h2_{t-2}
#pragma unroll 8
      for (int kk = 0; kk < 16; kk++) {
        int k = q * 16 + kk;
        float4 a = *(const float4*)(sH2e + k * SHS + 4 * tm);
        ulonglong2 u2 = *(const ulonglong2*)(sUW2 + (256 + k) * 16 + 4 * tn);
        unsigned long long s0, s1, s2, s3;
        SPLAT2(s0, a.x); SPLAT2(s1, a.y); SPLAT2(s2, a.z); SPLAT2(s3, a.w);
        FMA2(acc2[0][0], s0, u2.x); FMA2(acc2[0][1], s0, u2.y);
        FMA2(acc2[1][0], s1, u2.x); FMA2(acc2[1][1], s1, u2.y);
        FMA2(acc2[2][0], s2, u2.x); FMA2(acc2[2][1], s2, u2.y);
        FMA2(acc2[3][0], s3, u2.x); FMA2(acc2[3][1], s3, u2.y);
      }
      // scalar stores into [q][col16][bl] (2-way max)
#pragma unroll
      for (int r = 0; r < 4; r++) {
#pragma unroll
        for (int p = 0; p < 2; p++) {
          float lo = __uint_as_float((unsigned)(acc2[r][p] & 0xffffffffu));
          float hi = __uint_as_float((unsigned)(acc2[r][p] >> 32));
          sZp2[(q * 16 + 4 * tn + 2 * p)     * ZP2S + 4 * tm + r] = lo;
          sZp2[(q * 16 + 4 * tn + 2 * p + 1) * ZP2S + 4 * tm + r] = hi;
        }
      }
      __syncthreads();                                 // S7

      // L2 epilogue
      if (tid < 128) {
        float z[4];
#pragma unroll
        for (int g = 0; g < 4; g++) {
          float s = b2g[g];
#pragma unroll
          for (int q2 = 0; q2 < 8; q2++)
            s += sZp2[(q2 * 16 + g * 4 + uu2) * ZP2S + bl];
          z[g] = s;
        }
        float ig = 1.f / (1.f + __expf(-z[0]));
        float fg = 1.f / (1.f + __expf(-z[1]));
        float gg = fmaxf(z[2], 0.f);
        float og = 1.f / (1.f + __expf(-z[3]));
        c2 = fg * c2 + ig * gg;
        float h = og * fmaxf(c2, 0.f);
        if (t < TSTEPS)
          g_hseq2[(size_t)t * UN2 * BATCH + (size_t)u_g2 * BATCH + b_g] = h;
        else
          out_last[b_g * UN2 + u_g2] = h;
      }
      __syncthreads();                                 // S8 (h2 sealed)
    }
    if (tid == 0 && t < TSTEPS)
      asm volatile("red.release.gpu.global.add.u32 [%0], %1;" :: "l"(barB), "r"(1u));

    // ---- stage sX for t+1 ----
    if (t + 1 < TSTEPS) {
      for (int i = tid; i < 512; i += 256) {
        int bb = i >> 4, f4 = (i & 15) << 2;
        float4 v = *(const float4*)(x + (size_t)(b0 + bb) * TSTEPS * FEAT
                                      + (size_t)(t + 1) * FEAT + f4);
        sX[(f4 + 0) * SXS + bb] = v.x;
        sX[(f4 + 1) * SXS + bb] = v.y;
        sX[(f4 + 2) * SXS + bb] = v.z;
        sX[(f4 + 3) * SXS + bb] = v.w;
      }
    }
  }

  // ---- exit: last CTA of bg resets counters for next graph replay ----
  __syncthreads();
  if (tid == 0) {
    __threadfence();
    if (atomicAdd(exitc, 1u) + 1u == 32u) {
      *barA = 0u;
      *barB = 0u;
      *exitc = 0u;
    }
  }
}

// ---------------- launch --------------------------------------------------------
extern "C" void kernel_launch(void* const* d_in, const int* in_sizes, int n_in,
                              void* d_out, int out_size) {
  const float* x   = (const float*)d_in[0];
  const float* W1  = (const float*)d_in[1];
  const float* U1m = (const float*)d_in[2];
  const float* b1  = (const float*)d_in[3];
  const float* W2  = (const float*)d_in[4];
  const float* U2m = (const float*)d_in[5];
  const float* b2  = (const float*)d_in[6];
  float* out = (float*)d_out;

  constexpr int SMEM = (256 * 32 + 64 * 32 + 384 * 16 + 256 * 36 + 128 * 36 +
                        64 * 33 + 8 * 32 * 33 + 8 * 16 * 34) * 4;   // 180480 B
  cudaFuncSetAttribute(lstm_fused, cudaFuncAttributeMaxDynamicSharedMemorySize, SMEM);

  lstm_fused<<<128, 256, SMEM>>>(x, W1, U1m, b1, W2, U2m, b2, out);
}

// round 8
// speedup vs baseline: 1.0947x; 1.0947x over previous
#include <cuda_runtime.h>

#define BATCH  128
#define TSTEPS 512
#define FEAT   64
#define UN1    256
#define UN2    128

// packed fp32x2 FMA (Blackwell): two fp32 FMAs per instruction
#define FMA2(acc, a, b) \
  asm("fma.rn.f32x2 %0, %1, %2, %0;" : "+l"(acc) : "l"(a), "l"(b))
#define SPLAT2(dst, x) \
  asm("mov.b64 %0, {%1, %1};" : "=l"(dst) : "r"(__float_as_uint(x)))

#define CP_ASYNC16(saddr, gaddr) \
  asm volatile("cp.async.cg.shared.global [%0], [%1], 16;" :: "r"(saddr), "l"(gaddr))
#define CP_COMMIT() asm volatile("cp.async.commit_group;")
#define CP_WAIT0()  asm volatile("cp.async.wait_group 0;")

// ---------------- scratch ------------------------------------------------------
__device__ float g_hseq1[(size_t)(TSTEPS + 1) * UN1 * BATCH];  // [t][u][b], slot0 = 0
__device__ float g_hseq2[(size_t)(TSTEPS + 1) * UN2 * BATCH];  // [t][u][b], slot0 = 0
__device__ unsigned g_bar[4], g_exit[4];                       // per batch-group

// ---------------- fused persistent 2-layer LSTM --------------------------------
// 128 CTAs = 4 bg (32 batches) x 32 ug. ONE barrier per step (R6 protocol).
// Iteration t: L1 computes h1_t (t<512); L2 computes h2_{t-1} (t>=1).
// L1-h and L2-W2 passes over sH are MERGED into one k-loop.
__global__ void __launch_bounds__(256)
lstm_fused(const float* __restrict__ x,
           const float* __restrict__ W1, const float* __restrict__ U1m,
           const float* __restrict__ b1,
           const float* __restrict__ W2, const float* __restrict__ U2m,
           const float* __restrict__ b2,
           float* __restrict__ out_last) {
  constexpr int SHS  = 36;   // sH / sH2e row stride
  constexpr int SXS  = 33;   // sX row stride (2-way writes, CF scalar reads)
  constexpr int ZPS  = 33;   // sZp1: [q*32+col][bl], 2-way st, CF ld
  constexpr int ZP2S = 34;   // sZp2: [q*16+col][bl], 2-way st, CF ld

  extern __shared__ float smem[];
  float* sU1  = smem;                   // [256][32]
  float* sW1x = sU1 + 256 * 32;         // [64][32]
  float* sUW2 = sW1x + 64 * 32;         // [384][16]  W2 | U2
  float* sH   = sUW2 + 384 * 16;        // [256][SHS] h1_{t-1} [k][b]
  float* sH2e = sH + 256 * SHS;         // [128][SHS] h2_{t-2} [k][b]
  float* sX   = sH2e + 128 * SHS;       // [64][SXS]  x_t [f][b]
  float* sZp1 = sX + 64 * SXS;          // [8*32][ZPS]
  float* sZp2 = sZp1 + 8 * 32 * ZPS;    // [8*16][ZP2S]

  const int tid = threadIdx.x;
  const int bg  = blockIdx.x >> 5;
  const int ug  = blockIdx.x & 31;
  const int b0  = bg * 32;
  unsigned* bar   = &g_bar[bg];
  unsigned* exitc = &g_exit[bg];

  // ---- weight slices (once) ----
  for (int i = tid; i < 256 * 32; i += 256) {
    int k = i >> 5, cc = i & 31;
    sU1[i] = U1m[(size_t)k * 1024 + (cc >> 3) * 256 + ug * 8 + (cc & 7)];
  }
  for (int i = tid; i < 64 * 32; i += 256) {
    int k = i >> 5, cc = i & 31;
    sW1x[i] = W1[(size_t)k * 1024 + (cc >> 3) * 256 + ug * 8 + (cc & 7)];
  }
  for (int i = tid; i < 384 * 16; i += 256) {
    int k = i >> 4, c = i & 15;
    int col = (c >> 2) * 128 + ug * 4 + (c & 3);
    sUW2[i] = (k < 256) ? W2[(size_t)k * 512 + col]
                        : U2m[(size_t)(k - 256) * 512 + col];
  }

  // ---- thread mappings ----
  const int q  = tid >> 5;           // warp = k-slice
  const int li = tid & 31;
  const int tm = li >> 2;            // rows 4*tm..+3
  const int tn = li & 3;             // gate

  const int uu  = tid >> 5;          // L1 epilogue unit
  const int bl  = tid & 31;
  const int b_g = b0 + bl;
  const int u_g = ug * 8 + uu;
  const int uu2  = (tid >> 5) & 3;   // L2 epilogue unit (tid<128)
  const int u_g2 = ug * 4 + uu2;

  float c1 = 0.f, c2 = 0.f;
  float b1g[4], b2g[4];
#pragma unroll
  for (int g = 0; g < 4; g++) b1g[g] = b1[g * 256 + u_g];
  if (tid < 128) {
#pragma unroll
    for (int g = 0; g < 4; g++) b2g[g] = b2[g * 128 + u_g2];
  }

  const unsigned sH_u   = (unsigned)__cvta_generic_to_shared(sH);
  const unsigned sH2e_u = (unsigned)__cvta_generic_to_shared(sH2e);

  // ---- init h_{-1}, first arrive, stage sX(t=0) ----
  g_hseq1[(size_t)u_g * BATCH + b_g] = 0.f;
  if (tid < 128) g_hseq2[(size_t)u_g2 * BATCH + b_g] = 0.f;
  __syncthreads();
  if (tid == 0)
    asm volatile("red.release.gpu.global.add.u32 [%0], %1;" :: "l"(bar), "r"(1u));
  for (int i = tid; i < 512; i += 256) {
    int bb = i >> 4, f4 = (i & 15) << 2;
    float4 v = *(const float4*)(x + (size_t)(b0 + bb) * TSTEPS * FEAT + f4);
    sX[(f4 + 0) * SXS + bb] = v.x;
    sX[(f4 + 1) * SXS + bb] = v.y;
    sX[(f4 + 2) * SXS + bb] = v.z;
    sX[(f4 + 3) * SXS + bb] = v.w;
  }

  for (int t = 0; t <= TSTEPS; t++) {
    // ---- wait: h1_{t-1} and h2_{t-2} sealed ----
    if (tid == 0) {
      const unsigned tgt = (unsigned)(t + 1) * 32u;
      unsigned v;
      do {
        asm volatile("ld.relaxed.gpu.global.u32 %0, [%1];" : "=r"(v) : "l"(bar));
      } while (v < tgt);
      asm volatile("ld.acquire.gpu.global.u32 %0, [%1];" : "=r"(v) : "l"(bar));
    }
    __syncthreads();                                   // S1

    // ---- issue async staging: sH = h1_{t-1}; sH2e = h2_{t-2} ----
    {
      const float* hp = g_hseq1 + (size_t)t * UN1 * BATCH + b0;
#pragma unroll
      for (int j = 0; j < 8; j++) {
        int i = tid + j * 256;
        int k = i >> 3, b4 = (i & 7) << 2;
        CP_ASYNC16(sH_u + (unsigned)(k * SHS + b4) * 4u,
                   hp + (size_t)k * BATCH + b4);
      }
    }
    if (t >= 1) {
      const float* hp = g_hseq2 + (size_t)(t - 1) * UN2 * BATCH + b0;
#pragma unroll
      for (int j = 0; j < 4; j++) {
        int i = tid + j * 256;
        int k = i >> 3, b4 = (i & 7) << 2;
        CP_ASYNC16(sH2e_u + (unsigned)(k * SHS + b4) * 4u,
                   hp + (size_t)k * BATCH + b4);
      }
    }
    CP_COMMIT();

    // ---- L1 x-part while copies fly (sX staged previous iteration) ----
    unsigned long long acc[4][4];
    unsigned long long acc2[4][2];
#pragma unroll
    for (int r = 0; r < 4; r++) {
#pragma unroll
      for (int c = 0; c < 4; c++) acc[r][c] = 0ull;
      acc2[r][0] = 0ull; acc2[r][1] = 0ull;
    }
#pragma unroll
    for (int kk = 0; kk < 8; kk++) {
      int k = q * 8 + kk;
      const float* ap = sX + k * SXS + 4 * tm;
      float a0 = ap[0], a1 = ap[1], a2 = ap[2], a3 = ap[3];
      ulonglong2 uA = *(const ulonglong2*)(sW1x + k * 32 + 8 * tn);
      ulonglong2 uB = *(const ulonglong2*)(sW1x + k * 32 + 8 * tn + 4);
      unsigned long long s0, s1, s2, s3;
      SPLAT2(s0, a0); SPLAT2(s1, a1); SPLAT2(s2, a2); SPLAT2(s3, a3);
      FMA2(acc[0][0], s0, uA.x); FMA2(acc[0][1], s0, uA.y);
      FMA2(acc[0][2], s0, uB.x); FMA2(acc[0][3], s0, uB.y);
      FMA2(acc[1][0], s1, uA.x); FMA2(acc[1][1], s1, uA.y);
      FMA2(acc[1][2], s1, uB.x); FMA2(acc[1][3], s1, uB.y);
      FMA2(acc[2][0], s2, uA.x); FMA2(acc[2][1], s2, uA.y);
      FMA2(acc[2][2], s2, uB.x); FMA2(acc[2][3], s2, uB.y);
      FMA2(acc[3][0], s3, uA.x); FMA2(acc[3][1], s3, uA.y);
      FMA2(acc[3][2], s3, uB.x); FMA2(acc[3][3], s3, uB.y);
    }
    CP_WAIT0();
    __syncthreads();                                   // S2

    // ---- MERGED loop over sH: L1 U1-part + L2 W2-part (one a-load per k) ----
#pragma unroll 4
    for (int kk = 0; kk < 32; kk++) {
      int k = q * 32 + kk;
      float4 a = *(const float4*)(sH + k * SHS + 4 * tm);
      ulonglong2 uA = *(const ulonglong2*)(sU1 + k * 32 + 8 * tn);
      ulonglong2 uB = *(const ulonglong2*)(sU1 + k * 32 + 8 * tn + 4);
      ulonglong2 u2 = *(const ulonglong2*)(sUW2 + k * 16 + 4 * tn);
      unsigned long long s0, s1, s2, s3;
      SPLAT2(s0, a.x); SPLAT2(s1, a.y); SPLAT2(s2, a.z); SPLAT2(s3, a.w);
      FMA2(acc[0][0], s0, uA.x); FMA2(acc[0][1], s0, uA.y);
      FMA2(acc[0][2], s0, uB.x); FMA2(acc[0][3], s0, uB.y);
      FMA2(acc2[0][0], s0, u2.x); FMA2(acc2[0][1], s0, u2.y);
      FMA2(acc[1][0], s1, uA.x); FMA2(acc[1][1], s1, uA.y);
      FMA2(acc[1][2], s1, uB.x); FMA2(acc[1][3], s1, uB.y);
      FMA2(acc2[1][0], s1, u2.x); FMA2(acc2[1][1], s1, u2.y);
      FMA2(acc[2][0], s2, uA.x); FMA2(acc[2][1], s2, uA.y);
      FMA2(acc[2][2], s2, uB.x); FMA2(acc[2][3], s2, uB.y);
      FMA2(acc2[2][0], s2, u2.x); FMA2(acc2[2][1], s2, u2.y);
      FMA2(acc[3][0], s3, uA.x); FMA2(acc[3][1], s3, uA.y);
      FMA2(acc[3][2], s3, uB.x); FMA2(acc[3][3], s3, uB.y);
      FMA2(acc2[3][0], s3, u2.x); FMA2(acc2[3][1], s3, u2.y);
    }

    // ---- L2 U2-part over sH2e ----
#pragma unroll 8
    for (int kk = 0; kk < 16; kk++) {
      int k = q * 16 + kk;
      float4 a = *(const float4*)(sH2e + k * SHS + 4 * tm);
      ulonglong2 u2 = *(const ulonglong2*)(sUW2 + (256 + k) * 16 + 4 * tn);
      unsigned long long s0, s1, s2, s3;
      SPLAT2(s0, a.x); SPLAT2(s1, a.y); SPLAT2(s2, a.z); SPLAT2(s3, a.w);
      FMA2(acc2[0][0], s0, u2.x); FMA2(acc2[0][1], s0, u2.y);
      FMA2(acc2[1][0], s1, u2.x); FMA2(acc2[1][1], s1, u2.y);
      FMA2(acc2[2][0], s2, u2.x); FMA2(acc2[2][1], s2, u2.y);
      FMA2(acc2[3][0], s3, u2.x); FMA2(acc2[3][1], s3, u2.y);
    }

    // ---- partial stores (conflict-free [col][bl] layout) ----
#pragma unroll
    for (int r = 0; r < 4; r++) {
#pragma unroll
      for (int p = 0; p < 4; p++) {
        float lo = __uint_as_float((unsigned)(acc[r][p] & 0xffffffffu));
        float hi = __uint_as_float((unsigned)(acc[r][p] >> 32));
        sZp1[(q * 32 + 8 * tn + 2 * p)     * ZPS + 4 * tm + r] = lo;
        sZp1[(q * 32 + 8 * tn + 2 * p + 1) * ZPS + 4 * tm + r] = hi;
      }
#pragma unroll
      for (int p = 0; p < 2; p++) {
        float lo = __uint_as_float((unsigned)(acc2[r][p] & 0xffffffffu));
        float hi = __uint_as_float((unsigned)(acc2[r][p] >> 32));
        sZp2[(q * 16 + 4 * tn + 2 * p)     * ZP2S + 4 * tm + r] = lo;
        sZp2[(q * 16 + 4 * tn + 2 * p + 1) * ZP2S + 4 * tm + r] = hi;
      }
    }
    __syncthreads();                                   // S3

    // ---- L1 epilogue ----
    if (t < TSTEPS) {
      float z[4];
#pragma unroll
      for (int g = 0; g < 4; g++) {
        float s = b1g[g];
#pragma unroll
        for (int q2 = 0; q2 < 8; q2++)
          s += sZp1[(q2 * 32 + g * 8 + uu) * ZPS + bl];
        z[g] = s;
      }
      float ig = 1.f / (1.f + __expf(-z[0]));
      float fg = 1.f / (1.f + __expf(-z[1]));
      float gg = fmaxf(z[2], 0.f);
      float og = 1.f / (1.f + __expf(-z[3]));
      c1 = fg * c1 + ig * gg;
      float h = og * fmaxf(c1, 0.f);
      g_hseq1[(size_t)(t + 1) * UN1 * BATCH + (size_t)u_g * BATCH + b_g] = h;
    }
    // ---- L2 epilogue (computes h2_{t-1}) ----
    if (t >= 1 && tid < 128) {
      float z[4];
#pragma unroll
      for (int g = 0; g < 4; g++) {
        float s = b2g[g];
#pragma unroll
        for (int q2 = 0; q2 < 8; q2++)
          s += sZp2[(q2 * 16 + g * 4 + uu2) * ZP2S + bl];
        z[g] = s;
      }
      float ig = 1.f / (1.f + __expf(-z[0]));
      float fg = 1.f / (1.f + __expf(-z[1]));
      float gg = fmaxf(z[2], 0.f);
      float og = 1.f / (1.f + __expf(-z[3]));
      c2 = fg * c2 + ig * gg;
      float h = og * fmaxf(c2, 0.f);
      if (t < TSTEPS)
        g_hseq2[(size_t)t * UN2 * BATCH + (size_t)u_g2 * BATCH + b_g] = h;
      else
        out_last[b_g * UN2 + u_g2] = h;
    }
    __syncthreads();                                   // S4 (h stores sealed)

    // ---- arrive, then stage sX for t+1 in the barrier shadow ----
    if (tid == 0 && t < TSTEPS)
      asm volatile("red.release.gpu.global.add.u32 [%0], %1;" :: "l"(bar), "r"(1u));
    if (t + 1 < TSTEPS) {
      for (int i = tid; i < 512; i += 256) {
        int bb = i >> 4, f4 = (i & 15) << 2;
        float4 v = *(const float4*)(x + (size_t)(b0 + bb) * TSTEPS * FEAT
                                      + (size_t)(t + 1) * FEAT + f4);
        sX[(f4 + 0) * SXS + bb] = v.x;
        sX[(f4 + 1) * SXS + bb] = v.y;
        sX[(f4 + 2) * SXS + bb] = v.z;
        sX[(f4 + 3) * SXS + bb] = v.w;
      }
    }
  }

  // ---- exit: last CTA of bg resets counters for next graph replay ----
  __syncthreads();
  if (tid == 0) {
    __threadfence();
    if (atomicAdd(exitc, 1u) + 1u == 32u) {
      *bar = 0u;
      *exitc = 0u;
    }
  }
}

// ---------------- launch --------------------------------------------------------
extern "C" void kernel_launch(void* const* d_in, const int* in_sizes, int n_in,
                              void* d_out, int out_size) {
  const float* x   = (const float*)d_in[0];
  const float* W1  = (const float*)d_in[1];
  const float* U1m = (const float*)d_in[2];
  const float* b1  = (const float*)d_in[3];
  const float* W2  = (const float*)d_in[4];
  const float* U2m = (const float*)d_in[5];
  const float* b2  = (const float*)d_in[6];
  float* out = (float*)d_out;

  constexpr int SMEM = (256 * 32 + 64 * 32 + 384 * 16 + 256 * 36 + 128 * 36 +
                        64 * 33 + 8 * 32 * 33 + 8 * 16 * 34) * 4;   // 180480 B
  cudaFuncSetAttribute(lstm_fused, cudaFuncAttributeMaxDynamicSharedMemorySize, SMEM);

  lstm_fused<<<128, 256, SMEM>>>(x, W1, U1m, b1, W2, U2m, b2, out);
}

// round 9
// speedup vs baseline: 1.1900x; 1.0870x over previous
#include <cuda_runtime.h>

#define BATCH  128
#define TSTEPS 512
#define FEAT   64
#define UN1    256
#define UN2    128

// packed fp32x2 FMA (Blackwell): two fp32 FMAs per instruction
#define FMA2(acc, a, b) \
  asm("fma.rn.f32x2 %0, %1, %2, %0;" : "+l"(acc) : "l"(a), "l"(b))
#define SPLAT2(dst, x) \
  asm("mov.b64 %0, {%1, %1};" : "=l"(dst) : "r"(__float_as_uint(x)))

#define CP_ASYNC16(saddr, gaddr) \
  asm volatile("cp.async.cg.shared.global [%0], [%1], 16;" :: "r"(saddr), "l"(gaddr))
#define CP_COMMIT() asm volatile("cp.async.commit_group;")
#define CP_WAIT0()  asm volatile("cp.async.wait_group 0;")

// ---------------- scratch ------------------------------------------------------
__device__ float g_hseq1[(size_t)(TSTEPS + 1) * UN1 * BATCH];  // [t][u][b], slot0 = 0
__device__ float g_hseq2[(size_t)(TSTEPS + 1) * UN2 * BATCH];  // [t][u][b], slot0 = 0
__device__ unsigned g_bar[4], g_exit[4];                       // per batch-group

// ---------------- fused persistent 2-layer LSTM --------------------------------
// 128 CTAs = 4 bg (32 batches) x 32 ug; 512 threads = 16 warps.
// Warp w: q = w>>1 (k-slice), half = w&1 (column half). Same 8 partial slices.
__global__ void __launch_bounds__(512)
lstm_fused(const float* __restrict__ x,
           const float* __restrict__ W1, const float* __restrict__ U1m,
           const float* __restrict__ b1,
           const float* __restrict__ W2, const float* __restrict__ U2m,
           const float* __restrict__ b2,
           float* __restrict__ out_last) {
  constexpr int SHS  = 36;   // sH / sH2e row stride
  constexpr int SXS  = 33;   // sX row stride
  constexpr int ZPS  = 33;   // sZp1: [q*32+col][bl]
  constexpr int ZP2S = 34;   // sZp2: [q*16+col][bl]

  extern __shared__ float smem[];
  float* sU1  = smem;                   // [256][32]
  float* sW1x = sU1 + 256 * 32;         // [64][32]
  float* sUW2 = sW1x + 64 * 32;         // [384][16]  W2 | U2
  float* sH   = sUW2 + 384 * 16;        // [256][SHS] h1_{t-1} [k][b]
  float* sH2e = sH + 256 * SHS;         // [128][SHS] h2_{t-2} [k][b]
  float* sX   = sH2e + 128 * SHS;       // [64][SXS]  x_t [f][b]
  float* sZp1 = sX + 64 * SXS;          // [8*32][ZPS]
  float* sZp2 = sZp1 + 8 * 32 * ZPS;    // [8*16][ZP2S]

  const int tid = threadIdx.x;
  const int bg  = blockIdx.x >> 5;
  const int ug  = blockIdx.x & 31;
  const int b0  = bg * 32;
  unsigned* bar   = &g_bar[bg];
  unsigned* exitc = &g_exit[bg];

  // ---- weight slices (once) ----
  for (int i = tid; i < 256 * 32; i += 512) {
    int k = i >> 5, cc = i & 31;
    sU1[i] = U1m[(size_t)k * 1024 + (cc >> 3) * 256 + ug * 8 + (cc & 7)];
  }
  for (int i = tid; i < 64 * 32; i += 512) {
    int k = i >> 5, cc = i & 31;
    sW1x[i] = W1[(size_t)k * 1024 + (cc >> 3) * 256 + ug * 8 + (cc & 7)];
  }
  for (int i = tid; i < 384 * 16; i += 512) {
    int k = i >> 4, c = i & 15;
    int col = (c >> 2) * 128 + ug * 4 + (c & 3);
    sUW2[i] = (k < 256) ? W2[(size_t)k * 512 + col]
                        : U2m[(size_t)(k - 256) * 512 + col];
  }

  // ---- thread mappings (compute) ----
  const int w    = tid >> 5;
  const int q    = w >> 1;           // k-slice 0..7
  const int half = w & 1;            // column half
  const int li   = tid & 31;
  const int tm   = li >> 2;          // rows 4*tm..+3
  const int tn   = li & 3;           // gate

  // epilogue mappings
  const int uu  = tid >> 5;          // L1 unit (valid for tid<256)
  const int bl  = tid & 31;
  const int b_g = b0 + bl;
  const int u_g = ug * 8 + (uu & 7);
  const int uu2  = (tid >> 5) & 3;   // L2 unit (tid<128)
  const int u_g2 = ug * 4 + uu2;

  float c1 = 0.f, c2 = 0.f;
  float b1g[4], b2g[4];
  if (tid < 256) {
#pragma unroll
    for (int g = 0; g < 4; g++) b1g[g] = b1[g * 256 + u_g];
  }
  if (tid < 128) {
#pragma unroll
    for (int g = 0; g < 4; g++) b2g[g] = b2[g * 128 + u_g2];
  }

  const unsigned sH_u   = (unsigned)__cvta_generic_to_shared(sH);
  const unsigned sH2e_u = (unsigned)__cvta_generic_to_shared(sH2e);

  // ---- init h_{-1}, first arrive, stage sX(t=0) ----
  if (tid < 256) g_hseq1[(size_t)u_g * BATCH + b_g] = 0.f;
  if (tid < 128) g_hseq2[(size_t)u_g2 * BATCH + b_g] = 0.f;
  __syncthreads();
  if (tid == 0)
    asm volatile("red.release.gpu.global.add.u32 [%0], %1;" :: "l"(bar), "r"(1u));
  if (tid < 512) {
    int bb = tid >> 4, f4 = (tid & 15) << 2;
    float4 v = *(const float4*)(x + (size_t)(b0 + bb) * TSTEPS * FEAT + f4);
    sX[(f4 + 0) * SXS + bb] = v.x;
    sX[(f4 + 1) * SXS + bb] = v.y;
    sX[(f4 + 2) * SXS + bb] = v.z;
    sX[(f4 + 3) * SXS + bb] = v.w;
  }

  for (int t = 0; t <= TSTEPS; t++) {
    // ---- wait: h1_{t-1} and h2_{t-2} sealed ----
    if (tid == 0) {
      const unsigned tgt = (unsigned)(t + 1) * 32u;
      unsigned v;
      do {
        asm volatile("ld.relaxed.gpu.global.u32 %0, [%1];" : "=r"(v) : "l"(bar));
      } while (v < tgt);
      asm volatile("ld.acquire.gpu.global.u32 %0, [%1];" : "=r"(v) : "l"(bar));
    }
    __syncthreads();                                   // S1

    // ---- issue async staging: sH = h1_{t-1}; sH2e = h2_{t-2} ----
    {
      const float* hp = g_hseq1 + (size_t)t * UN1 * BATCH + b0;
#pragma unroll
      for (int j = 0; j < 4; j++) {
        int i = tid + j * 512;
        int k = i >> 3, b4 = (i & 7) << 2;
        CP_ASYNC16(sH_u + (unsigned)(k * SHS + b4) * 4u,
                   hp + (size_t)k * BATCH + b4);
      }
    }
    if (t >= 1) {
      const float* hp = g_hseq2 + (size_t)(t - 1) * UN2 * BATCH + b0;
#pragma unroll
      for (int j = 0; j < 2; j++) {
        int i = tid + j * 512;
        int k = i >> 3, b4 = (i & 7) << 2;
        CP_ASYNC16(sH2e_u + (unsigned)(k * SHS + b4) * 4u,
                   hp + (size_t)k * BATCH + b4);
      }
    }
    CP_COMMIT();

    // ---- L1 x-part while copies fly ----
    unsigned long long acc[4][2];   // 4 rows x 4 L1 cols
    unsigned long long acc2[4];     // 4 rows x 2 L2 cols
#pragma unroll
    for (int r = 0; r < 4; r++) {
      acc[r][0] = 0ull; acc[r][1] = 0ull; acc2[r] = 0ull;
    }
#pragma unroll
    for (int kk = 0; kk < 8; kk++) {
      int k = q * 8 + kk;
      const float* ap = sX + k * SXS + 4 * tm;
      float a0 = ap[0], a1 = ap[1], a2 = ap[2], a3 = ap[3];
      ulonglong2 uA = *(const ulonglong2*)(sW1x + k * 32 + 8 * tn + 4 * half);
      unsigned long long s0, s1, s2, s3;
      SPLAT2(s0, a0); SPLAT2(s1, a1); SPLAT2(s2, a2); SPLAT2(s3, a3);
      FMA2(acc[0][0], s0, uA.x); FMA2(acc[0][1], s0, uA.y);
      FMA2(acc[1][0], s1, uA.x); FMA2(acc[1][1], s1, uA.y);
      FMA2(acc[2][0], s2, uA.x); FMA2(acc[2][1], s2, uA.y);
      FMA2(acc[3][0], s3, uA.x); FMA2(acc[3][1], s3, uA.y);
    }
    CP_WAIT0();
    __syncthreads();                                   // S2

    // ---- MERGED loop over sH: L1 U1-part + L2 W2-part ----
#pragma unroll 4
    for (int kk = 0; kk < 32; kk++) {
      int k = q * 32 + kk;
      float4 a = *(const float4*)(sH + k * SHS + 4 * tm);
      ulonglong2 uA = *(const ulonglong2*)(sU1 + k * 32 + 8 * tn + 4 * half);
      unsigned long long u2 = *(const unsigned long long*)(sUW2 + k * 16 + 4 * tn + 2 * half);
      unsigned long long s0, s1, s2, s3;
      SPLAT2(s0, a.x); SPLAT2(s1, a.y); SPLAT2(s2, a.z); SPLAT2(s3, a.w);
      FMA2(acc[0][0], s0, uA.x); FMA2(acc[0][1], s0, uA.y); FMA2(acc2[0], s0, u2);
      FMA2(acc[1][0], s1, uA.x); FMA2(acc[1][1], s1, uA.y); FMA2(acc2[1], s1, u2);
      FMA2(acc[2][0], s2, uA.x); FMA2(acc[2][1], s2, uA.y); FMA2(acc2[2], s2, u2);
      FMA2(acc[3][0], s3, uA.x); FMA2(acc[3][1], s3, uA.y); FMA2(acc2[3], s3, u2);
    }

    // ---- L2 U2-part over sH2e ----
#pragma unroll 8
    for (int kk = 0; kk < 16; kk++) {
      int k = q * 16 + kk;
      float4 a = *(const float4*)(sH2e + k * SHS + 4 * tm);
      unsigned long long u2 = *(const unsigned long long*)(sUW2 + (256 + k) * 16 + 4 * tn + 2 * half);
      unsigned long long s0, s1, s2, s3;
      SPLAT2(s0, a.x); SPLAT2(s1, a.y); SPLAT2(s2, a.z); SPLAT2(s3, a.w);
      FMA2(acc2[0], s0, u2);
      FMA2(acc2[1], s1, u2);
      FMA2(acc2[2], s2, u2);
      FMA2(acc2[3], s3, u2);
    }

    // ---- partial stores ([col][bl] layout; halves write disjoint cols) ----
#pragma unroll
    for (int r = 0; r < 4; r++) {
#pragma unroll
      for (int p = 0; p < 2; p++) {
        float lo = __uint_as_float((unsigned)(acc[r][p] & 0xffffffffu));
        float hi = __uint_as_float((unsigned)(acc[r][p] >> 32));
        sZp1[(q * 32 + 8 * tn + 4 * half + 2 * p)     * ZPS + 4 * tm + r] = lo;
        sZp1[(q * 32 + 8 * tn + 4 * half + 2 * p + 1) * ZPS + 4 * tm + r] = hi;
      }
      {
        float lo = __uint_as_float((unsigned)(acc2[r] & 0xffffffffu));
        float hi = __uint_as_float((unsigned)(acc2[r] >> 32));
        sZp2[(q * 16 + 4 * tn + 2 * half)     * ZP2S + 4 * tm + r] = lo;
        sZp2[(q * 16 + 4 * tn + 2 * half + 1) * ZP2S + 4 * tm + r] = hi;
      }
    }
    __syncthreads();                                   // S3

    // ---- L1 epilogue (threads 0..255) ----
    if (t < TSTEPS && tid < 256) {
      float z[4];
#pragma unroll
      for (int g = 0; g < 4; g++) {
        float s = b1g[g];
#pragma unroll
        for (int q2 = 0; q2 < 8; q2++)
          s += sZp1[(q2 * 32 + g * 8 + uu) * ZPS + bl];
        z[g] = s;
      }
      float ig = 1.f / (1.f + __expf(-z[0]));
      float fg = 1.f / (1.f + __expf(-z[1]));
      float gg = fmaxf(z[2], 0.f);
      float og = 1.f / (1.f + __expf(-z[3]));
      c1 = fg * c1 + ig * gg;
      float h = og * fmaxf(c1, 0.f);
      g_hseq1[(size_t)(t + 1) * UN1 * BATCH + (size_t)u_g * BATCH + b_g] = h;
    }
    // ---- L2 epilogue (threads 0..127; computes h2_{t-1}) ----
    if (t >= 1 && tid < 128) {
      float z[4];
#pragma unroll
      for (int g = 0; g < 4; g++) {
        float s = b2g[g];
#pragma unroll
        for (int q2 = 0; q2 < 8; q2++)
          s += sZp2[(q2 * 16 + g * 4 + uu2) * ZP2S + bl];
        z[g] = s;
      }
      float ig = 1.f / (1.f + __expf(-z[0]));
      float fg = 1.f / (1.f + __expf(-z[1]));
      float gg = fmaxf(z[2], 0.f);
      float og = 1.f / (1.f + __expf(-z[3]));
      c2 = fg * c2 + ig * gg;
      float h = og * fmaxf(c2, 0.f);
      if (t < TSTEPS)
        g_hseq2[(size_t)t * UN2 * BATCH + (size_t)u_g2 * BATCH + b_g] = h;
      else
        out_last[b_g * UN2 + u_g2] = h;
    }
    __syncthreads();                                   // S4 (h stores sealed)

    // ---- arrive, then stage sX for t+1 in the barrier shadow ----
    if (tid == 0 && t < TSTEPS)
      asm volatile("red.release.gpu.global.add.u32 [%0], %1;" :: "l"(bar), "r"(1u));
    if (t + 1 < TSTEPS) {
      int bb = tid >> 4, f4 = (tid & 15) << 2;
      float4 v = *(const float4*)(x + (size_t)(b0 + bb) * TSTEPS * FEAT
                                    + (size_t)(t + 1) * FEAT + f4);
      sX[(f4 + 0) * SXS + bb] = v.x;
      sX[(f4 + 1) * SXS + bb] = v.y;
      sX[(f4 + 2) * SXS + bb] = v.z;
      sX[(f4 + 3) * SXS + bb] = v.w;
    }
  }

  // ---- exit: last CTA of bg resets counters for next graph replay ----
  __syncthreads();
  if (tid == 0) {
    __threadfence();
    if (atomicAdd(exitc, 1u) + 1u == 32u) {
      *bar = 0u;
      *exitc = 0u;
    }
  }
}

// ---------------- launch --------------------------------------------------------
extern "C" void kernel_launch(void* const* d_in, const int* in_sizes, int n_in,
                              void* d_out, int out_size) {
  const float* x   = (const float*)d_in[0];
  const float* W1  = (const float*)d_in[1];
  const float* U1m = (const float*)d_in[2];
  const float* b1  = (const float*)d_in[3];
  const float* W2  = (const float*)d_in[4];
  const float* U2m = (const float*)d_in[5];
  const float* b2  = (const float*)d_in[6];
  float* out = (float*)d_out;

  constexpr int SMEM = (256 * 32 + 64 * 32 + 384 * 16 + 256 * 36 + 128 * 36 +
                        64 * 33 + 8 * 32 * 33 + 8 * 16 * 34) * 4;   // 180480 B
  cudaFuncSetAttribute(lstm_fused, cudaFuncAttributeMaxDynamicSharedMemorySize, SMEM);

  lstm_fused<<<128, 512, SMEM>>>(x, W1, U1m, b1, W2, U2m, b2, out);
}